// round 4
// baseline (speedup 1.0000x reference)
#include <cuda_runtime.h>
#include <math.h>
#include <stdint.h>

// Problem constants (fixed by dataset)
#define NL    4
#define Bz    64
#define Hd    512
#define Tmax  256
#define NCTA  128     // 512 units / 4 units per CTA
#define NTHR  256
#define KT    64
#define NTILE 16      // 1024 total K (512 Wih + 512 Whh) / 64

// Persistent state (device globals; no allocation allowed).
// Activations stored [unit][batch] so K-tiles are contiguous.
__device__ __align__(16) float g_x[Hd * Bz];            // transposed y (t=0 input)
__device__ __align__(16) float g_h[2][NL][Hd * Bz];     // ping-pong h per layer
__device__ unsigned g_bar;                              // grid barrier counter

__device__ __forceinline__ float sigm(float x) { return 1.0f / (1.0f + expf(-x)); }

// ---------------- prologue: reset barrier + transpose initial state ----------------
__global__ void lstm_prologue(const float* __restrict__ y, const float* __restrict__ h0) {
    if (blockIdx.x == 0 && threadIdx.x == 0) g_bar = 0u;
    int idx = blockIdx.x * blockDim.x + threadIdx.x;
    int stride = gridDim.x * blockDim.x;
    // y[b][u] -> g_x[u][b]
    for (int i = idx; i < Hd * Bz; i += stride) {
        int u = i >> 6, b = i & 63;
        g_x[u * Bz + b] = y[b * Hd + u];
    }
    // h0[l][b][u] -> g_h[1][l][u][b]  (t=0 reads prev buffer = 1)
    for (int i = idx; i < NL * Hd * Bz; i += stride) {
        int l = i >> 15;
        int r = i & 32767;
        int u = r >> 6, b = r & 63;
        g_h[1][l][u * Bz + b] = h0[(size_t)l * Bz * Hd + b * Hd + u];
    }
}

// ---------------- main persistent kernel ----------------
// CTA i owns units u0..u0+3 (u0 = 4i), i.e. gate rows {g*512+u}.
// Warp w (0..7): unit j = w>>1, batch half = w&1. Thread owns 1 batch column,
// 4 gate accumulators. K in 16 tiles of 64 (8 Wih tiles then 8 Whh tiles).
__global__ void __launch_bounds__(NTHR, 1) lstm_persistent(
    const float* __restrict__ c0,
    const float* __restrict__ Wih,
    const float* __restrict__ Whh,
    const float* __restrict__ bih,
    const float* __restrict__ bhh,
    const int*   __restrict__ seqp,
    float*       __restrict__ out)
{
    __shared__ __align__(16) float Xs[KT][Bz];   // [k][batch]  16KB
    __shared__ __align__(16) float Ws[16][KT];   // [lr][k], lr = unit*4 + gate, 4KB

    const int tid  = threadIdx.x;
    const int cta  = blockIdx.x;
    const int u0   = cta * 4;
    const int w    = tid >> 5;
    const int lane = tid & 31;
    const int j    = w >> 1;                 // unit-in-CTA 0..3
    const int u    = u0 + j;
    const int c    = ((w & 1) << 5) + lane;  // batch column 0..63

    // W-loader mapping: thread loads one 16B chunk of the 16x64 W tile
    const int lr   = tid >> 4;               // 0..15 = unit*4 + gate
    const int ck   = tid & 15;               // 16B chunk within row
    const int grow = (lr & 3) * Hd + u0 + (lr >> 2);  // global gate-row

    int T = Tmax;
    if (seqp) { int tv = *seqp; if (tv > 0 && tv <= Tmax) T = tv; }

    // c-state in registers (only this thread touches its (l,u,c) cells)
    float cst[NL];
#pragma unroll
    for (int l = 0; l < NL; l++)
        cst[l] = c0[(size_t)l * Bz * Hd + c * Hd + u];

    // combined biases
    float bias[NL][4];
#pragma unroll
    for (int l = 0; l < NL; l++)
#pragma unroll
        for (int g = 0; g < 4; g++) {
            int row = g * Hd + u;
            bias[l][g] = bih[l * 4 * Hd + row] + bhh[l * 4 * Hd + row];
        }

    unsigned rr = 0;  // completed rounds

    for (int t = 0; t < T; t++) {
        const int p = t & 1;
        const float* xbase0 = (t == 0) ? g_x : g_h[p ^ 1][NL - 1];

        for (int l = 0; l < NL; l++) {
            const float* inb = (l == 0) ? xbase0 : g_h[p][l - 1];  // layer input
            const float* hb  = g_h[p ^ 1][l];                      // h_{t-1}
            const float* Wi  = Wih + (size_t)l * 4 * Hd * Hd;
            const float* Wh  = Whh + (size_t)l * 4 * Hd * Hd;

            float aI = 0.f, aF = 0.f, aG = 0.f, aO = 0.f;

            float4 xr[4];
            float4 wr;

            // prefetch tile 0 into registers
            {
                const float4* xsrc = (const float4*)inb;           // tile 0 = Wih, kbase 0
                const float*  wsrc = Wi;
#pragma unroll
                for (int q = 0; q < 4; q++)
                    xr[q] = __ldcg(xsrc + tid + q * 256);
                wr = *((const float4*)(wsrc + (size_t)grow * Hd) + ck);
            }

            for (int tt = 0; tt < NTILE; tt++) {
                __syncthreads();  // previous tile's compute complete everywhere
                // store prefetched tile to smem
#pragma unroll
                for (int q = 0; q < 4; q++)
                    ((float4*)Xs)[tid + q * 256] = xr[q];
                *(float4*)&Ws[lr][ck * 4] = wr;

                // issue loads for next tile (overlaps with compute below)
                if (tt + 1 < NTILE) {
                    const int nt = tt + 1;
                    const float4* xsrc = (nt < 8)
                        ? (const float4*)(inb + nt * KT * Bz)
                        : (const float4*)(hb + (nt - 8) * KT * Bz);
                    const float* wsrc = (nt < 8) ? Wi : Wh;
                    const int kbase = (nt & 7) * KT;
#pragma unroll
                    for (int q = 0; q < 4; q++)
                        xr[q] = __ldcg(xsrc + tid + q * 256);
                    wr = *((const float4*)(wsrc + (size_t)grow * Hd + kbase) + ck);
                }
                __syncthreads();  // smem tile visible

#pragma unroll
                for (int k = 0; k < KT; k += 4) {
                    float4 wI = *(const float4*)&Ws[j * 4 + 0][k];
                    float4 wF = *(const float4*)&Ws[j * 4 + 1][k];
                    float4 wG = *(const float4*)&Ws[j * 4 + 2][k];
                    float4 wO = *(const float4*)&Ws[j * 4 + 3][k];
                    float x0 = Xs[k + 0][c];
                    float x1 = Xs[k + 1][c];
                    float x2 = Xs[k + 2][c];
                    float x3 = Xs[k + 3][c];

                    aI += wI.x * x0; aF += wF.x * x0; aG += wG.x * x0; aO += wO.x * x0;
                    aI += wI.y * x1; aF += wF.y * x1; aG += wG.y * x1; aO += wO.y * x1;
                    aI += wI.z * x2; aF += wF.z * x2; aG += wG.z * x2; aO += wO.z * x2;
                    aI += wI.w * x3; aF += wF.w * x3; aG += wG.w * x3; aO += wO.w * x3;
                }
            }

            // ---- elementwise epilogue (torch gate order i,f,g,o) ----
            float iG = sigm(aI + bias[l][0]);
            float fG = sigm(aF + bias[l][1]);
            float gG = tanhf(aG + bias[l][2]);
            float oG = sigm(aO + bias[l][3]);
            float cn = fG * cst[l] + iG * gG;
            cst[l] = cn;
            float hn = oG * tanhf(cn);

            __stcg(&g_h[p][l][u * Bz + c], hn);   // L2-visible, bypass L1

            if (l == NL - 1)
                out[((size_t)c * T + t) * Hd + u] = hn;  // out[b][t][u]

            // ---- grid barrier: release h to all CTAs ----
            __threadfence();
            __syncthreads();
            rr++;
            if (tid == 0) {
                atomicAdd(&g_bar, 1u);
                const unsigned target = rr * NCTA;
                volatile unsigned* vb = &g_bar;
                while (*vb < target) { }
            }
            __syncthreads();
        }
    }
}

extern "C" void kernel_launch(void* const* d_in, const int* in_sizes, int n_in,
                              void* d_out, int out_size) {
    const float* y   = (const float*)d_in[0];
    const float* h0  = (const float*)d_in[1];
    const float* c0  = (const float*)d_in[2];
    const float* Wih = (const float*)d_in[3];
    const float* Whh = (const float*)d_in[4];
    const float* bih = (const float*)d_in[5];
    const float* bhh = (const float*)d_in[6];
    const int*   sl  = (n_in >= 8) ? (const int*)d_in[7] : nullptr;
    float* out = (float*)d_out;
    (void)in_sizes; (void)out_size;

    lstm_prologue<<<128, 256>>>(y, h0);
    lstm_persistent<<<NCTA, NTHR>>>(c0, Wih, Whh, bih, bhh, sl, out);
}

// round 5
// speedup vs baseline: 2.9926x; 2.9926x over previous
#include <cuda_runtime.h>
#include <cuda_fp16.h>
#include <math.h>
#include <stdint.h>

// Problem constants (fixed by dataset)
#define NL    4
#define Bz    64
#define Hd    512
#define Tmax  256
#define NCTA  128
#define NTHR  256

// smem: resident Whi frags (4 layers x 64 ktiles x 32 lanes x 16B) + reduction buf
#define SMEM_WHI (4*64*32*8*2)   // 131072 B
#define SMEM_RED (8*16*64*4)     // 32768 B
#define SMEM_TOT (SMEM_WHI + SMEM_RED)

// ---------------- persistent device state (no allocation allowed) ----------------
// W packed in m16n8k16 A-fragment order: idx = (((cta*4+l)*64+kt)*32+lane)*8+hx
__device__ __align__(16) __half g_WhiP[8388608];   // 16 MB
__device__ __align__(16) __half g_WloP[8388608];   // 16 MB
// Activations packed in B-fragment order, 16B/lane = {b0hi,b1hi,b0lo,b1lo}
// plane = [32 ktiles][8 ntiles][32 lanes][8 halves] = 65536 halves
__device__ __align__(16) __half g_Xin [2][NL][65536];  // input to layer l (slot l), parity p
__device__ __align__(16) __half g_Hrec[2][NL][65536];  // recurrent h of layer l, parity p
__device__ unsigned g_bar;

__device__ __forceinline__ float sigm(float x) { return 1.0f / (1.0f + expf(-x)); }

// position of X element (k,n) inside a packed plane; o = hi half index, o+4 = lo
__device__ __forceinline__ int xbase(int k, int n) {
    int kt = k >> 4, kr = k & 15, nt = n >> 3, nc = n & 7;
    int lane = nc * 4 + ((kr >> 1) & 3);
    return ((kt * 8 + nt) * 32 + lane) * 8 + ((kr >> 3) * 2 + (kr & 1));
}

__device__ __forceinline__ void pack_x_plain(__half* plane, int k, int n, float v) {
    int o = xbase(k, n);
    __half hi = __float2half_rn(v);
    __half lo = __float2half_rn(v - __half2float(hi));
    plane[o]     = hi;
    plane[o + 4] = lo;
}

__device__ __forceinline__ void pack_x_cg(__half* plane, int k, int n, float v) {
    int o = xbase(k, n);
    __half hi = __float2half_rn(v);
    __half lo = __float2half_rn(v - __half2float(hi));
    __stcg((unsigned short*)&plane[o],     __half_as_ushort(hi));
    __stcg((unsigned short*)&plane[o + 4], __half_as_ushort(lo));
}

__device__ __forceinline__ void mma16816(float& c0, float& c1, float& c2, float& c3,
                                         unsigned a0, unsigned a1, unsigned a2, unsigned a3,
                                         unsigned b0, unsigned b1) {
    asm volatile(
        "mma.sync.aligned.m16n8k16.row.col.f32.f16.f16.f32 "
        "{%0,%1,%2,%3}, {%4,%5,%6,%7}, {%8,%9}, {%0,%1,%2,%3};\n"
        : "+f"(c0), "+f"(c1), "+f"(c2), "+f"(c3)
        : "r"(a0), "r"(a1), "r"(a2), "r"(a3), "r"(b0), "r"(b1));
}

// ---------------- prologue 1: pack weights into fragment layout (hi/lo fp16) ----------------
__global__ void pack_weights(const float* __restrict__ Wih, const float* __restrict__ Whh) {
    int idx = blockIdx.x * 256 + threadIdx.x;          // 0 .. 8388607
    int hx   = idx & 7;
    int lane = (idx >> 3) & 31;
    int kt   = (idx >> 8) & 63;
    int l    = (idx >> 14) & 3;
    int cta  = idx >> 16;
    int areg = hx >> 1, h = hx & 1;
    int r    = (lane >> 2) + (areg & 1) * 8;           // A row 0..15
    int kcol = (lane & 3) * 2 + (areg >> 1) * 8 + h;   // A col 0..15
    int unit = r >> 2, gate = r & 3;
    int grow = gate * Hd + cta * 4 + unit;             // global gate row
    const float* W = (kt < 32) ? Wih : Whh;
    int kk = (kt & 31) * 16 + kcol;
    float v = W[(size_t)l * 4 * Hd * Hd + (size_t)grow * Hd + kk];
    __half hi = __float2half_rn(v);
    __half lo = __float2half_rn(v - __half2float(hi));
    g_WhiP[idx] = hi;
    g_WloP[idx] = lo;
}

// ---------------- prologue 2: pack initial state ----------------
__global__ void pack_state(const float* __restrict__ y, const float* __restrict__ h0) {
    int i = blockIdx.x * 256 + threadIdx.x;            // 0 .. 163839
    if (i == 0) g_bar = 0u;
    if (i < Hd * Bz) {                                  // y[b][u] -> Xin[0][0]
        int u = i >> 6, b = i & 63;
        pack_x_plain(&g_Xin[0][0][0], u, b, y[b * Hd + u]);
    } else {
        int j2 = i - Hd * Bz;                           // h0[l][b][u] -> Hrec[0][l]
        int l = j2 >> 15;
        int r2 = j2 & 32767;
        int u = r2 >> 6, b = r2 & 63;
        pack_x_plain(&g_Hrec[0][l][0], u, b, h0[(size_t)l * Bz * Hd + b * Hd + u]);
    }
}

// ---------------- main persistent kernel ----------------
// CTA owns 16 gate rows (4 units x 4 gates). 8 warps partition K=1024 (128 each):
// warps 0-3 read Xin ktiles 0..31, warps 4-7 read Hrec ktiles 0..31.
__global__ void __launch_bounds__(NTHR, 1) lstm_mma(
    const float* __restrict__ c0,
    const float* __restrict__ bih,
    const float* __restrict__ bhh,
    const int*   __restrict__ seqp,
    float*       __restrict__ out)
{
    extern __shared__ char sm[];
    __half* sWhi = (__half*)sm;                 // [4][64][32][8]
    float*  red  = (float*)(sm + SMEM_WHI);     // [8 warps][16 rows][64 cols]

    const int tid  = threadIdx.x;
    const int cta  = blockIdx.x;
    const int w    = tid >> 5;
    const int lane = tid & 31;

    // load resident Whi fragments (131072 B = 8192 uint4)
    {
        const uint4* src = (const uint4*)&g_WhiP[(size_t)cta * 65536];
        uint4* dst = (uint4*)sWhi;
#pragma unroll 4
        for (int i = tid; i < 8192; i += NTHR) dst[i] = src[i];
    }

    // epilogue mapping: thread -> (unit j, batch c)
    const int j = tid >> 6;
    const int c = tid & 63;
    const int u = cta * 4 + j;

    float cst[NL];
#pragma unroll
    for (int l = 0; l < NL; l++)
        cst[l] = c0[(size_t)l * Bz * Hd + c * Hd + u];

    float bias[NL][4];
#pragma unroll
    for (int l = 0; l < NL; l++)
#pragma unroll
        for (int g = 0; g < 4; g++)
            bias[l][g] = bih[l * 4 * Hd + g * Hd + u] + bhh[l * 4 * Hd + g * Hd + u];

    int T = Tmax;
    if (seqp) { int tv = *seqp; if (tv > 0 && tv <= Tmax) T = tv; }

    __syncthreads();

    const int ktbase = w * 8;
    const int ktl0   = (w < 4) ? ktbase : (ktbase - 32);
    const uint4* sA0   = (const uint4*)sWhi;
    const uint4* gAlo0 = (const uint4*)g_WloP + (size_t)cta * 8192;

    unsigned rr = 0;

    for (int t = 0; t < T; t++) {
        const int p = t & 1;
        for (int l = 0; l < NL; l++) {
            const uint4* Bbase = (w < 4) ? (const uint4*)&g_Xin[p][l][0]
                                         : (const uint4*)&g_Hrec[p][l][0];
            const uint4* sA   = sA0   + (l * 64 + ktbase) * 32 + lane;
            const uint4* gAlo = gAlo0 + (l * 64 + ktbase) * 32 + lane;

            float acc[8][4];
#pragma unroll
            for (int nt = 0; nt < 8; nt++)
#pragma unroll
                for (int q = 0; q < 4; q++) acc[nt][q] = 0.f;

#pragma unroll
            for (int kt8 = 0; kt8 < 8; kt8++) {
                uint4 ahi = sA[kt8 * 32];
                uint4 alo = __ldcg(gAlo + kt8 * 32);
                uint4 bb[8];
#pragma unroll
                for (int nt = 0; nt < 8; nt++)
                    bb[nt] = __ldcg(Bbase + (((ktl0 + kt8) * 8 + nt) * 32 + lane));
#pragma unroll
                for (int nt = 0; nt < 8; nt++) {
                    mma16816(acc[nt][0], acc[nt][1], acc[nt][2], acc[nt][3],
                             ahi.x, ahi.y, ahi.z, ahi.w, bb[nt].x, bb[nt].y);   // Whi*Xhi
                    mma16816(acc[nt][0], acc[nt][1], acc[nt][2], acc[nt][3],
                             ahi.x, ahi.y, ahi.z, ahi.w, bb[nt].z, bb[nt].w);   // Whi*Xlo
                    mma16816(acc[nt][0], acc[nt][1], acc[nt][2], acc[nt][3],
                             alo.x, alo.y, alo.z, alo.w, bb[nt].x, bb[nt].y);   // Wlo*Xhi
                }
            }

            // cross-warp K reduction via smem
            {
                int gid = lane >> 2, tig = lane & 3;
#pragma unroll
                for (int nt = 0; nt < 8; nt++) {
                    *(float2*)&red[(w * 16 + gid)     * 64 + nt * 8 + tig * 2] =
                        make_float2(acc[nt][0], acc[nt][1]);
                    *(float2*)&red[(w * 16 + gid + 8) * 64 + nt * 8 + tig * 2] =
                        make_float2(acc[nt][2], acc[nt][3]);
                }
            }
            __syncthreads();

            float s0 = 0.f, s1 = 0.f, s2 = 0.f, s3 = 0.f;
#pragma unroll
            for (int ww = 0; ww < 8; ww++) {
                const float* rw = &red[(ww * 16 + j * 4) * 64 + c];
                s0 += rw[0]; s1 += rw[64]; s2 += rw[128]; s3 += rw[192];
            }

            float iG = sigm(s0 + bias[l][0]);
            float fG = sigm(s1 + bias[l][1]);
            float gG = tanhf(s2 + bias[l][2]);
            float oG = sigm(s3 + bias[l][3]);
            float cn = fG * cst[l] + iG * gG;
            cst[l] = cn;
            float hn = oG * tanhf(cn);

            // publish h: next-layer input slot + own recurrent slot (never read this round)
            __half* xdst = (l < NL - 1) ? &g_Xin[p][l + 1][0] : &g_Xin[p ^ 1][0][0];
            pack_x_cg(xdst, u, c, hn);
            pack_x_cg(&g_Hrec[p ^ 1][l][0], u, c, hn);
            if (l == NL - 1)
                out[((size_t)c * T + t) * Hd + u] = hn;   // out[b][t][u]

            // grid barrier
            __threadfence();
            __syncthreads();
            rr++;
            if (tid == 0) {
                atomicAdd(&g_bar, 1u);
                const unsigned target = rr * NCTA;
                volatile unsigned* vb = &g_bar;
                while (*vb < target) { }
            }
            __syncthreads();
        }
    }
}

extern "C" void kernel_launch(void* const* d_in, const int* in_sizes, int n_in,
                              void* d_out, int out_size) {
    const float* y   = (const float*)d_in[0];
    const float* h0  = (const float*)d_in[1];
    const float* c0  = (const float*)d_in[2];
    const float* Wih = (const float*)d_in[3];
    const float* Whh = (const float*)d_in[4];
    const float* bih = (const float*)d_in[5];
    const float* bhh = (const float*)d_in[6];
    const int*   sl  = (n_in >= 8) ? (const int*)d_in[7] : nullptr;
    float* out = (float*)d_out;
    (void)in_sizes; (void)out_size;

    cudaFuncSetAttribute(lstm_mma, cudaFuncAttributeMaxDynamicSharedMemorySize, SMEM_TOT);

    pack_weights<<<32768, 256>>>(Wih, Whh);
    pack_state<<<640, 256>>>(y, h0);
    lstm_mma<<<NCTA, NTHR, SMEM_TOT>>>(c0, bih, bhh, sl, out);
}

// round 6
// speedup vs baseline: 3.1413x; 1.0497x over previous
#include <cuda_runtime.h>
#include <cuda_fp16.h>
#include <math.h>
#include <stdint.h>

// Problem constants (fixed by dataset)
#define NL    4
#define Bz    64
#define Hd    512
#define Tmax  256
#define NCTA  128
#define NTHR  256

// smem: resident Whi frags (4 layers x 64 ktiles x 32 lanes x 16B) + reduction buf
#define SMEM_WHI (4*64*32*8*2)   // 131072 B
#define SMEM_RED (8*16*64*4)     // 32768 B
#define SMEM_TOT (SMEM_WHI + SMEM_RED)

// ---------------- persistent device state (no allocation allowed) ----------------
// W packed in m16n8k16 A-fragment order: idx = (((cta*4+l)*64+kt)*32+lane)*8+hx
__device__ __align__(16) __half g_WhiP[8388608];   // 16 MB
__device__ __align__(16) __half g_WloP[8388608];   // 16 MB
// Activations packed in B-fragment order, 16B/lane = {b0hi,b1hi,b0lo,b1lo}
// plane = [32 ktiles][8 ntiles][32 lanes][8 halves] = 65536 halves
__device__ __align__(16) __half g_Xin [2][NL][65536];  // input to layer l, parity p
__device__ __align__(16) __half g_Hrec[2][NL][65536];  // recurrent h of layer l, parity p
__device__ unsigned g_bar;

__device__ __forceinline__ float sigm(float x) { return 1.0f / (1.0f + expf(-x)); }

// position of X element (k,n) inside a packed plane; o = hi half index, o+4 = lo
__device__ __forceinline__ int xbase(int k, int n) {
    int kt = k >> 4, kr = k & 15, nt = n >> 3, nc = n & 7;
    int lane = nc * 4 + ((kr >> 1) & 3);
    return ((kt * 8 + nt) * 32 + lane) * 8 + ((kr >> 3) * 2 + (kr & 1));
}

__device__ __forceinline__ void pack_x_plain(__half* plane, int k, int n, float v) {
    int o = xbase(k, n);
    __half hi = __float2half_rn(v);
    __half lo = __float2half_rn(v - __half2float(hi));
    plane[o]     = hi;
    plane[o + 4] = lo;
}

__device__ __forceinline__ void pack_x_cg(__half* plane, int k, int n, float v) {
    int o = xbase(k, n);
    __half hi = __float2half_rn(v);
    __half lo = __float2half_rn(v - __half2float(hi));
    __stcg((unsigned short*)&plane[o],     __half_as_ushort(hi));
    __stcg((unsigned short*)&plane[o + 4], __half_as_ushort(lo));
}

__device__ __forceinline__ void mma16816(float* c,
                                         unsigned a0, unsigned a1, unsigned a2, unsigned a3,
                                         unsigned b0, unsigned b1) {
    asm volatile(
        "mma.sync.aligned.m16n8k16.row.col.f32.f16.f16.f32 "
        "{%0,%1,%2,%3}, {%4,%5,%6,%7}, {%8,%9}, {%0,%1,%2,%3};\n"
        : "+f"(c[0]), "+f"(c[1]), "+f"(c[2]), "+f"(c[3])
        : "r"(a0), "r"(a1), "r"(a2), "r"(a3), "r"(b0), "r"(b1));
}

// ---------------- prologue 1: pack weights into fragment layout (hi/lo fp16) ----------------
__global__ void pack_weights(const float* __restrict__ Wih, const float* __restrict__ Whh) {
    int idx = blockIdx.x * 256 + threadIdx.x;          // 0 .. 8388607
    int hx   = idx & 7;
    int lane = (idx >> 3) & 31;
    int kt   = (idx >> 8) & 63;
    int l    = (idx >> 14) & 3;
    int cta  = idx >> 16;
    int areg = hx >> 1, h = hx & 1;
    int r    = (lane >> 2) + (areg & 1) * 8;           // A row 0..15
    int kcol = (lane & 3) * 2 + (areg >> 1) * 8 + h;   // A col 0..15
    int unit = r >> 2, gate = r & 3;
    int grow = gate * Hd + cta * 4 + unit;             // global gate row
    const float* W = (kt < 32) ? Wih : Whh;
    int kk = (kt & 31) * 16 + kcol;
    float v = W[(size_t)l * 4 * Hd * Hd + (size_t)grow * Hd + kk];
    __half hi = __float2half_rn(v);
    __half lo = __float2half_rn(v - __half2float(hi));
    g_WhiP[idx] = hi;
    g_WloP[idx] = lo;
}

// ---------------- prologue 2: pack initial state ----------------
__global__ void pack_state(const float* __restrict__ y, const float* __restrict__ h0) {
    int i = blockIdx.x * 256 + threadIdx.x;            // 0 .. 163839
    if (i == 0) g_bar = 0u;
    if (i < Hd * Bz) {                                  // y[b][u] -> Xin[0][0]
        int u = i >> 6, b = i & 63;
        pack_x_plain(&g_Xin[0][0][0], u, b, y[b * Hd + u]);
    } else {
        int j2 = i - Hd * Bz;                           // h0[l][b][u] -> Hrec[0][l]
        int l = j2 >> 15;
        int r2 = j2 & 32767;
        int u = r2 >> 6, b = r2 & 63;
        pack_x_plain(&g_Hrec[0][l][0], u, b, h0[(size_t)l * Bz * Hd + b * Hd + u]);
    }
}

// ---------------- half-GEMM: 4 ktiles, 8 ntiles, 3 MMA terms, pipelined loads ----------------
// sA / gAlo pre-offset to (layer, first ktile)*32 + lane. Bplane is the packed
// activation plane; kt0 = plane-local first ktile (= 4*warp).
__device__ __forceinline__ void half_mma(
    float acc[8][4], const uint4* __restrict__ sA, const uint4* __restrict__ gAlo,
    const uint4* __restrict__ Bplane, int kt0, int lane)
{
    uint4 bb[2][8];
    uint4 alo[2];
    alo[0] = __ldcg(gAlo);
#pragma unroll
    for (int nt = 0; nt < 8; nt++)
        bb[0][nt] = __ldcg(Bplane + (((kt0) * 8 + nt) * 32 + lane));

#pragma unroll
    for (int q = 0; q < 4; q++) {
        const int cur = q & 1, nxt = cur ^ 1;
        if (q < 3) {
            alo[nxt] = __ldcg(gAlo + (q + 1) * 32);
#pragma unroll
            for (int nt = 0; nt < 8; nt++)
                bb[nxt][nt] = __ldcg(Bplane + (((kt0 + q + 1) * 8 + nt) * 32 + lane));
        }
        uint4 ahi = sA[q * 32];
#pragma unroll
        for (int nt = 0; nt < 8; nt++) {
            mma16816(acc[nt], ahi.x, ahi.y, ahi.z, ahi.w, bb[cur][nt].x, bb[cur][nt].y); // Whi*Xhi
            mma16816(acc[nt], ahi.x, ahi.y, ahi.z, ahi.w, bb[cur][nt].z, bb[cur][nt].w); // Whi*Xlo
            mma16816(acc[nt], alo[cur].x, alo[cur].y, alo[cur].z, alo[cur].w,
                     bb[cur][nt].x, bb[cur][nt].y);                                      // Wlo*Xhi
        }
    }
}

// ---------------- main persistent kernel ----------------
// CTA owns 16 gate rows (4 units x 4 gates). All 8 warps split each 32-ktile
// plane (4 ktiles each). Hrec half of round r+1 is computed between arrive(r)
// and wait(r) — it only depends on data from round r-3.
__global__ void __launch_bounds__(NTHR, 1) lstm_mma(
    const float* __restrict__ c0,
    const float* __restrict__ bih,
    const float* __restrict__ bhh,
    const int*   __restrict__ seqp,
    float*       __restrict__ out)
{
    extern __shared__ char sm[];
    __half* sWhi = (__half*)sm;                 // [4][64][32][8]
    float*  red  = (float*)(sm + SMEM_WHI);     // [8 warps][16 rows][64 cols]

    const int tid  = threadIdx.x;
    const int cta  = blockIdx.x;
    const int w    = tid >> 5;
    const int lane = tid & 31;

    // load resident Whi fragments (131072 B = 8192 uint4)
    {
        const uint4* src = (const uint4*)&g_WhiP[(size_t)cta * 65536];
        uint4* dst = (uint4*)sWhi;
#pragma unroll 4
        for (int i = tid; i < 8192; i += NTHR) dst[i] = src[i];
    }

    // epilogue mapping: thread -> (unit j, batch c)
    const int j = tid >> 6;
    const int c = tid & 63;
    const int u = cta * 4 + j;

    float cst[NL];
#pragma unroll
    for (int l = 0; l < NL; l++)
        cst[l] = c0[(size_t)l * Bz * Hd + c * Hd + u];

    float bias[NL][4];
#pragma unroll
    for (int l = 0; l < NL; l++)
#pragma unroll
        for (int g = 0; g < 4; g++)
            bias[l][g] = bih[l * 4 * Hd + g * Hd + u] + bhh[l * 4 * Hd + g * Hd + u];

    int T = Tmax;
    if (seqp) { int tv = *seqp; if (tv > 0 && tv <= Tmax) T = tv; }
    const int R = NL * T;

    __syncthreads();

    const int kt0 = w * 4;                       // plane-local first ktile for this warp
    const uint4* sA0   = (const uint4*)sWhi;
    const uint4* gAlo0 = (const uint4*)g_WloP + (size_t)cta * 8192;

    float acc[8][4];
#pragma unroll
    for (int nt = 0; nt < 8; nt++)
#pragma unroll
        for (int q = 0; q < 4; q++) acc[nt][q] = 0.f;

    // Hrec half for round 0 (t=0, l=0, p=0): reads prologue-packed data
    half_mma(acc, sA0 + (0 * 64 + 32 + kt0) * 32 + lane,
             gAlo0 + (0 * 64 + 32 + kt0) * 32 + lane,
             (const uint4*)&g_Hrec[0][0][0], kt0, lane);

    for (int r = 0; r < R; r++) {
        const int t = r >> 2, l = r & 3, p = t & 1;

        // wait(r-1): all CTAs finished round r-1 -> Xin plane for round r is ready
        if (r > 0) {
            if (tid == 0) {
                const unsigned target = (unsigned)r * NCTA;
                volatile unsigned* vb = &g_bar;
                while (*vb < target) { }
            }
            __syncthreads();
        }

        // Xin half of round r (critical path)
        half_mma(acc, sA0 + (l * 64 + kt0) * 32 + lane,
                 gAlo0 + (l * 64 + kt0) * 32 + lane,
                 (const uint4*)&g_Xin[p][l][0], kt0, lane);

        // cross-warp K reduction via smem
        {
            int gid = lane >> 2, tig = lane & 3;
#pragma unroll
            for (int nt = 0; nt < 8; nt++) {
                *(float2*)&red[(w * 16 + gid)     * 64 + nt * 8 + tig * 2] =
                    make_float2(acc[nt][0], acc[nt][1]);
                *(float2*)&red[(w * 16 + gid + 8) * 64 + nt * 8 + tig * 2] =
                    make_float2(acc[nt][2], acc[nt][3]);
            }
        }
        __syncthreads();

        float s0 = 0.f, s1 = 0.f, s2 = 0.f, s3 = 0.f;
#pragma unroll
        for (int ww = 0; ww < 8; ww++) {
            const float* rw = &red[(ww * 16 + j * 4) * 64 + c];
            s0 += rw[0]; s1 += rw[64]; s2 += rw[128]; s3 += rw[192];
        }

        float iG = sigm(s0 + bias[l][0]);
        float fG = sigm(s1 + bias[l][1]);
        float gG = tanhf(s2 + bias[l][2]);
        float oG = sigm(s3 + bias[l][3]);
        float cn = fG * cst[l] + iG * gG;
        cst[l] = cn;
        float hn = oG * tanhf(cn);

        // publish h: next-layer input slot + own recurrent slot (never read this round)
        __half* xdst = (l < NL - 1) ? &g_Xin[p][l + 1][0] : &g_Xin[p ^ 1][0][0];
        pack_x_cg(xdst, u, c, hn);
        pack_x_cg(&g_Hrec[p ^ 1][l][0], u, c, hn);
        if (l == NL - 1)
            out[((size_t)c * T + t) * Hd + u] = hn;   // out[b][t][u]

        __threadfence();
        __syncthreads();           // all publishes done; also guards red reuse
        if (tid == 0) atomicAdd(&g_bar, 1u);   // arrive(r)

        // Hrec half of round r+1 — runs in the shadow of other CTAs' skew.
        // Its source was written at round r-3, already ordered by wait(r-1).
        if (r + 1 < R) {
#pragma unroll
            for (int nt = 0; nt < 8; nt++)
#pragma unroll
                for (int q = 0; q < 4; q++) acc[nt][q] = 0.f;
            const int r2 = r + 1, l2 = r2 & 3, p2 = (r2 >> 2) & 1;
            half_mma(acc, sA0 + (l2 * 64 + 32 + kt0) * 32 + lane,
                     gAlo0 + (l2 * 64 + 32 + kt0) * 32 + lane,
                     (const uint4*)&g_Hrec[p2][l2][0], kt0, lane);
        }
    }
}

extern "C" void kernel_launch(void* const* d_in, const int* in_sizes, int n_in,
                              void* d_out, int out_size) {
    const float* y   = (const float*)d_in[0];
    const float* h0  = (const float*)d_in[1];
    const float* c0  = (const float*)d_in[2];
    const float* Wih = (const float*)d_in[3];
    const float* Whh = (const float*)d_in[4];
    const float* bih = (const float*)d_in[5];
    const float* bhh = (const float*)d_in[6];
    const int*   sl  = (n_in >= 8) ? (const int*)d_in[7] : nullptr;
    float* out = (float*)d_out;
    (void)in_sizes; (void)out_size;

    cudaFuncSetAttribute(lstm_mma, cudaFuncAttributeMaxDynamicSharedMemorySize, SMEM_TOT);

    pack_weights<<<32768, 256>>>(Wih, Whh);
    pack_state<<<640, 256>>>(y, h0);
    lstm_mma<<<NCTA, NTHR, SMEM_TOT>>>(c0, bih, bhh, sl, out);
}

// round 7
// speedup vs baseline: 4.3507x; 1.3850x over previous
#include <cuda_runtime.h>
#include <cuda_fp16.h>
#include <math.h>
#include <stdint.h>

// Problem constants (fixed by dataset)
#define NL    4
#define Bz    64
#define Hd    512
#define Tmax  256
#define NCTA  128
#define NTHR  256

// smem: resident Whi frags (4 layers x 64 ktiles x 32 lanes x 16B) + reduction buf
#define SMEM_WHI (4*64*32*8*2)   // 131072 B
#define SMEM_RED (8*16*64*4)     // 32768 B
#define SMEM_TOT (SMEM_WHI + SMEM_RED)

// ---------------- persistent device state (no allocation allowed) ----------------
// W packed in m16n8k16 A-fragment order: idx = (((cta*4+l)*64+kt)*32+lane)*8+hx
__device__ __align__(16) __half g_WhiP[8388608];   // 16 MB
__device__ __align__(16) __half g_WloP[8388608];   // 16 MB
// Activations packed in B-fragment order, single fp16, 8B/lane = {b0,b1}
// plane = [32 ktiles][8 ntiles][32 lanes][4 halves] = 32768 halves
__device__ __align__(16) __half g_Xin [2][NL][32768];  // input to layer l, parity p
__device__ __align__(16) __half g_Hrec[2][NL][32768];  // recurrent h of layer l, parity p
__device__ unsigned g_bar;

__device__ __forceinline__ float sigm(float x) { return 1.0f / (1.0f + expf(-x)); }

// offset of X element (k,n) inside a packed plane (single fp16)
__device__ __forceinline__ int xoff(int k, int n) {
    int kt = k >> 4, kr = k & 15, nt = n >> 3, nc = n & 7;
    int lane = nc * 4 + ((kr >> 1) & 3);
    return ((kt * 8 + nt) * 32 + lane) * 4 + ((kr >> 3) * 2 + (kr & 1));
}

__device__ __forceinline__ void mma16816(float* c,
                                         unsigned a0, unsigned a1, unsigned a2, unsigned a3,
                                         unsigned b0, unsigned b1) {
    asm volatile(
        "mma.sync.aligned.m16n8k16.row.col.f32.f16.f16.f32 "
        "{%0,%1,%2,%3}, {%4,%5,%6,%7}, {%8,%9}, {%0,%1,%2,%3};\n"
        : "+f"(c[0]), "+f"(c[1]), "+f"(c[2]), "+f"(c[3])
        : "r"(a0), "r"(a1), "r"(a2), "r"(a3), "r"(b0), "r"(b1));
}

// ---------------- prologue 1: pack weights into fragment layout (hi/lo fp16) ----------------
__global__ void pack_weights(const float* __restrict__ Wih, const float* __restrict__ Whh) {
    int idx = blockIdx.x * 256 + threadIdx.x;          // 0 .. 8388607
    int hx   = idx & 7;
    int lane = (idx >> 3) & 31;
    int kt   = (idx >> 8) & 63;
    int l    = (idx >> 14) & 3;
    int cta  = idx >> 16;
    int areg = hx >> 1, h = hx & 1;
    int r    = (lane >> 2) + (areg & 1) * 8;           // A row 0..15
    int kcol = (lane & 3) * 2 + (areg >> 1) * 8 + h;   // A col 0..15
    int unit = r >> 2, gate = r & 3;
    int grow = gate * Hd + cta * 4 + unit;             // global gate row
    const float* W = (kt < 32) ? Wih : Whh;
    int kk = (kt & 31) * 16 + kcol;
    float v = W[(size_t)l * 4 * Hd * Hd + (size_t)grow * Hd + kk];
    __half hi = __float2half_rn(v);
    __half lo = __float2half_rn(v - __half2float(hi));
    g_WhiP[idx] = hi;
    g_WloP[idx] = lo;
}

// ---------------- prologue 2: pack initial state (single fp16) ----------------
__global__ void pack_state(const float* __restrict__ y, const float* __restrict__ h0) {
    int i = blockIdx.x * 256 + threadIdx.x;            // 0 .. 163839
    if (i == 0) g_bar = 0u;
    if (i < Hd * Bz) {                                  // y[b][u] -> Xin[0][0]
        int u = i >> 6, b = i & 63;
        g_Xin[0][0][xoff(u, b)] = __float2half_rn(y[b * Hd + u]);
    } else {
        int j2 = i - Hd * Bz;                           // h0[l][b][u] -> Hrec[0][l]
        int l = j2 >> 15;
        int r2 = j2 & 32767;
        int u = r2 >> 6, b = r2 & 63;
        g_Hrec[0][l][xoff(u, b)] =
            __float2half_rn(h0[(size_t)l * Bz * Hd + b * Hd + u]);
    }
}

// ---------------- half-GEMM: 4 ktiles, 8 ntiles, 2 MMA terms, pipelined loads ----------------
// sA / gAlo pre-offset to (layer, first ktile)*32 + lane. Bplane is the packed
// activation plane (uint2 fragments); kt0 = plane-local first ktile (= 4*warp).
__device__ __forceinline__ void half_mma(
    float acc[8][4], const uint4* __restrict__ sA, const uint4* __restrict__ gAlo,
    const uint2* __restrict__ Bplane, int kt0, int lane)
{
    uint2 bb[2][8];
    uint4 alo[2];
    alo[0] = __ldcg(gAlo);
#pragma unroll
    for (int nt = 0; nt < 8; nt++)
        bb[0][nt] = __ldcg(Bplane + (((kt0) * 8 + nt) * 32 + lane));

#pragma unroll
    for (int q = 0; q < 4; q++) {
        const int cur = q & 1, nxt = cur ^ 1;
        if (q < 3) {
            alo[nxt] = __ldcg(gAlo + (q + 1) * 32);
#pragma unroll
            for (int nt = 0; nt < 8; nt++)
                bb[nxt][nt] = __ldcg(Bplane + (((kt0 + q + 1) * 8 + nt) * 32 + lane));
        }
        uint4 ahi = sA[q * 32];
#pragma unroll
        for (int nt = 0; nt < 8; nt++) {
            mma16816(acc[nt], ahi.x, ahi.y, ahi.z, ahi.w,
                     bb[cur][nt].x, bb[cur][nt].y);                     // Whi*X
            mma16816(acc[nt], alo[cur].x, alo[cur].y, alo[cur].z, alo[cur].w,
                     bb[cur][nt].x, bb[cur][nt].y);                     // Wlo*X
        }
    }
}

// ---------------- main persistent kernel ----------------
// CTA owns 16 gate rows (4 units x 4 gates). All 8 warps split each 32-ktile
// plane (4 ktiles each). Hrec half of round r+1 is computed between arrive(r)
// and wait(r) — it only depends on data from round r-3.
__global__ void __launch_bounds__(NTHR, 1) lstm_mma(
    const float* __restrict__ c0,
    const float* __restrict__ bih,
    const float* __restrict__ bhh,
    const int*   __restrict__ seqp,
    float*       __restrict__ out)
{
    extern __shared__ char sm[];
    __half* sWhi = (__half*)sm;                 // [4][64][32][8]
    float*  red  = (float*)(sm + SMEM_WHI);     // [8 warps][16 rows][64 cols]

    const int tid  = threadIdx.x;
    const int cta  = blockIdx.x;
    const int w    = tid >> 5;
    const int lane = tid & 31;

    // load resident Whi fragments (131072 B = 8192 uint4)
    {
        const uint4* src = (const uint4*)&g_WhiP[(size_t)cta * 65536];
        uint4* dst = (uint4*)sWhi;
#pragma unroll 4
        for (int i = tid; i < 8192; i += NTHR) dst[i] = src[i];
    }

    // epilogue mapping: thread -> (unit j, batch c)
    const int j = tid >> 6;
    const int c = tid & 63;
    const int u = cta * 4 + j;
    const int xo = xoff(u, c);   // publish offset in packed planes

    float cst[NL];
#pragma unroll
    for (int l = 0; l < NL; l++)
        cst[l] = c0[(size_t)l * Bz * Hd + c * Hd + u];

    float bias[NL][4];
#pragma unroll
    for (int l = 0; l < NL; l++)
#pragma unroll
        for (int g = 0; g < 4; g++)
            bias[l][g] = bih[l * 4 * Hd + g * Hd + u] + bhh[l * 4 * Hd + g * Hd + u];

    int T = Tmax;
    if (seqp) { int tv = *seqp; if (tv > 0 && tv <= Tmax) T = tv; }
    const int R = NL * T;

    __syncthreads();

    const int kt0 = w * 4;                       // plane-local first ktile for this warp
    const uint4* sA0   = (const uint4*)sWhi;
    const uint4* gAlo0 = (const uint4*)g_WloP + (size_t)cta * 8192;

    float acc[8][4];
#pragma unroll
    for (int nt = 0; nt < 8; nt++)
#pragma unroll
        for (int q = 0; q < 4; q++) acc[nt][q] = 0.f;

    // Hrec half for round 0 (t=0, l=0, p=0): reads prologue-packed data
    half_mma(acc, sA0 + (0 * 64 + 32 + kt0) * 32 + lane,
             gAlo0 + (0 * 64 + 32 + kt0) * 32 + lane,
             (const uint2*)&g_Hrec[0][0][0], kt0, lane);

    for (int r = 0; r < R; r++) {
        const int t = r >> 2, l = r & 3, p = t & 1;

        // wait(r-1): all CTAs finished round r-1 -> Xin plane for round r is ready
        if (r > 0) {
            if (tid == 0) {
                const unsigned target = (unsigned)r * NCTA;
                volatile unsigned* vb = &g_bar;
                while (*vb < target) { }
            }
            __syncthreads();
        }

        // Xin half of round r (critical path)
        half_mma(acc, sA0 + (l * 64 + kt0) * 32 + lane,
                 gAlo0 + (l * 64 + kt0) * 32 + lane,
                 (const uint2*)&g_Xin[p][l][0], kt0, lane);

        // cross-warp K reduction via smem
        {
            int gid = lane >> 2, tig = lane & 3;
#pragma unroll
            for (int nt = 0; nt < 8; nt++) {
                *(float2*)&red[(w * 16 + gid)     * 64 + nt * 8 + tig * 2] =
                    make_float2(acc[nt][0], acc[nt][1]);
                *(float2*)&red[(w * 16 + gid + 8) * 64 + nt * 8 + tig * 2] =
                    make_float2(acc[nt][2], acc[nt][3]);
            }
        }
        __syncthreads();

        float s0 = 0.f, s1 = 0.f, s2 = 0.f, s3 = 0.f;
#pragma unroll
        for (int ww = 0; ww < 8; ww++) {
            const float* rw = &red[(ww * 16 + j * 4) * 64 + c];
            s0 += rw[0]; s1 += rw[64]; s2 += rw[128]; s3 += rw[192];
        }

        float iG = sigm(s0 + bias[l][0]);
        float fG = sigm(s1 + bias[l][1]);
        float gG = tanhf(s2 + bias[l][2]);
        float oG = sigm(s3 + bias[l][3]);
        float cn = fG * cst[l] + iG * gG;
        cst[l] = cn;
        float hn = oG * tanhf(cn);

        // publish h (single fp16): next-layer input slot + own recurrent slot
        {
            unsigned short hb = __half_as_ushort(__float2half_rn(hn));
            __half* xdst = (l < NL - 1) ? &g_Xin[p][l + 1][0] : &g_Xin[p ^ 1][0][0];
            __stcg((unsigned short*)&xdst[xo], hb);
            __stcg((unsigned short*)&g_Hrec[p ^ 1][l][xo], hb);
        }
        if (l == NL - 1)
            out[((size_t)c * T + t) * Hd + u] = hn;   // out[b][t][u]

        __threadfence();
        __syncthreads();           // all publishes done; also guards red reuse
        if (tid == 0) atomicAdd(&g_bar, 1u);   // arrive(r)

        // Hrec half of round r+1 — runs in the shadow of other CTAs' skew.
        // Its source was written at round r-3, already ordered by wait(r-1).
        if (r + 1 < R) {
#pragma unroll
            for (int nt = 0; nt < 8; nt++)
#pragma unroll
                for (int q = 0; q < 4; q++) acc[nt][q] = 0.f;
            const int r2 = r + 1, l2 = r2 & 3, p2 = (r2 >> 2) & 1;
            half_mma(acc, sA0 + (l2 * 64 + 32 + kt0) * 32 + lane,
                     gAlo0 + (l2 * 64 + 32 + kt0) * 32 + lane,
                     (const uint2*)&g_Hrec[p2][l2][0], kt0, lane);
        }
    }
}

extern "C" void kernel_launch(void* const* d_in, const int* in_sizes, int n_in,
                              void* d_out, int out_size) {
    const float* y   = (const float*)d_in[0];
    const float* h0  = (const float*)d_in[1];
    const float* c0  = (const float*)d_in[2];
    const float* Wih = (const float*)d_in[3];
    const float* Whh = (const float*)d_in[4];
    const float* bih = (const float*)d_in[5];
    const float* bhh = (const float*)d_in[6];
    const int*   sl  = (n_in >= 8) ? (const int*)d_in[7] : nullptr;
    float* out = (float*)d_out;
    (void)in_sizes; (void)out_size;

    cudaFuncSetAttribute(lstm_mma, cudaFuncAttributeMaxDynamicSharedMemorySize, SMEM_TOT);

    pack_weights<<<32768, 256>>>(Wih, Whh);
    pack_state<<<640, 256>>>(y, h0);
    lstm_mma<<<NCTA, NTHR, SMEM_TOT>>>(c0, bih, bhh, sl, out);
}

// round 9
// speedup vs baseline: 5.0502x; 1.1608x over previous
#include <cuda_runtime.h>
#include <cuda_fp16.h>
#include <math.h>
#include <stdint.h>

// Problem constants (fixed by dataset)
#define NL    4
#define Bz    64
#define Hd    512
#define Tmax  256
#define NCTA  128
#define NTHR  256

// smem: resident W frags (4 layers x 64 ktiles x 32 lanes x 16B) + reduction buf
#define SMEM_W   (4*64*32*8*2)   // 131072 B
#define SMEM_RED (8*16*64*4)     // 32768 B
#define SMEM_TOT (SMEM_W + SMEM_RED)

// ---------------- persistent device state (no allocation allowed) ----------------
// W packed in m16n8k16 A-fragment order: idx = (((cta*4+l)*64+kt)*32+lane)*8+hx
__device__ __align__(16) __half g_WP[8388608];   // 16 MB, fp16
// Activations packed in B-fragment order, single fp16, 8B/lane = {b0,b1}
// plane = [32 ktiles][8 ntiles][32 lanes][4 halves] = 32768 halves
__device__ __align__(16) __half g_Xin [2][NL][32768];  // input to layer l, parity p
__device__ __align__(16) __half g_Hrec[2][NL][32768];  // recurrent h of layer l, parity p
__device__ unsigned g_bar;

__device__ __forceinline__ float sigm(float x) { return 1.0f / (1.0f + expf(-x)); }

// offset of X element (k,n) inside a packed plane (single fp16)
__device__ __forceinline__ int xoff(int k, int n) {
    int kt = k >> 4, kr = k & 15, nt = n >> 3, nc = n & 7;
    int lane = nc * 4 + ((kr >> 1) & 3);
    return ((kt * 8 + nt) * 32 + lane) * 4 + ((kr >> 3) * 2 + (kr & 1));
}

__device__ __forceinline__ void mma16816(float* c,
                                         unsigned a0, unsigned a1, unsigned a2, unsigned a3,
                                         unsigned b0, unsigned b1) {
    asm volatile(
        "mma.sync.aligned.m16n8k16.row.col.f32.f16.f16.f32 "
        "{%0,%1,%2,%3}, {%4,%5,%6,%7}, {%8,%9}, {%0,%1,%2,%3};\n"
        : "+f"(c[0]), "+f"(c[1]), "+f"(c[2]), "+f"(c[3])
        : "r"(a0), "r"(a1), "r"(a2), "r"(a3), "r"(b0), "r"(b1));
}

// ---------------- prologue 1: pack weights into fragment layout (fp16) ----------------
__global__ void pack_weights(const float* __restrict__ Wih, const float* __restrict__ Whh) {
    int idx = blockIdx.x * 256 + threadIdx.x;          // 0 .. 8388607
    int hx   = idx & 7;
    int lane = (idx >> 3) & 31;
    int kt   = (idx >> 8) & 63;
    int l    = (idx >> 14) & 3;
    int cta  = idx >> 16;
    int areg = hx >> 1, h = hx & 1;
    int r    = (lane >> 2) + (areg & 1) * 8;           // A row 0..15
    int kcol = (lane & 3) * 2 + (areg >> 1) * 8 + h;   // A col 0..15
    int unit = r >> 2, gate = r & 3;
    int grow = gate * Hd + cta * 4 + unit;             // global gate row
    const float* W = (kt < 32) ? Wih : Whh;
    int kk = (kt & 31) * 16 + kcol;
    float v = W[(size_t)l * 4 * Hd * Hd + (size_t)grow * Hd + kk];
    g_WP[idx] = __float2half_rn(v);
}

// ---------------- prologue 2: pack initial state (single fp16) ----------------
__global__ void pack_state(const float* __restrict__ y, const float* __restrict__ h0) {
    int i = blockIdx.x * 256 + threadIdx.x;            // 0 .. 163839
    if (i == 0) g_bar = 0u;
    if (i < Hd * Bz) {                                  // y[b][u] -> Xin[0][0]
        int u = i >> 6, b = i & 63;
        g_Xin[0][0][xoff(u, b)] = __float2half_rn(y[b * Hd + u]);
    } else {
        int j2 = i - Hd * Bz;                           // h0[l][b][u] -> Hrec[0][l]
        int l = j2 >> 15;
        int r2 = j2 & 32767;
        int u = r2 >> 6, b = r2 & 63;
        g_Hrec[0][l][xoff(u, b)] =
            __float2half_rn(h0[(size_t)l * Bz * Hd + b * Hd + u]);
    }
}

// ---------------- half-GEMM: 4 ktiles, 8 ntiles, 1 MMA term, pipelined loads ----------------
// sA pre-offset to (layer, first ktile)*32 + lane. Bplane is the packed
// activation plane (uint2 fragments); kt0 = plane-local first ktile (= 4*warp).
__device__ __forceinline__ void half_mma(
    float acc[8][4], const uint4* __restrict__ sA,
    const uint2* __restrict__ Bplane, int kt0, int lane)
{
    uint2 bb[2][8];
#pragma unroll
    for (int nt = 0; nt < 8; nt++)
        bb[0][nt] = __ldcg(Bplane + (((kt0) * 8 + nt) * 32 + lane));

#pragma unroll
    for (int q = 0; q < 4; q++) {
        const int cur = q & 1, nxt = cur ^ 1;
        if (q < 3) {
#pragma unroll
            for (int nt = 0; nt < 8; nt++)
                bb[nxt][nt] = __ldcg(Bplane + (((kt0 + q + 1) * 8 + nt) * 32 + lane));
        }
        uint4 ahi = sA[q * 32];
#pragma unroll
        for (int nt = 0; nt < 8; nt++)
            mma16816(acc[nt], ahi.x, ahi.y, ahi.z, ahi.w,
                     bb[cur][nt].x, bb[cur][nt].y);                     // W*X
    }
}

// ---------------- main persistent kernel ----------------
// CTA owns 16 gate rows (4 units x 4 gates). All 8 warps split each 32-ktile
// plane (4 ktiles each). Hrec half of round r+1 is computed between arrive(r)
// and wait(r) — it only depends on data from round r-3.
__global__ void __launch_bounds__(NTHR, 1) lstm_mma(
    const float* __restrict__ c0,
    const float* __restrict__ bih,
    const float* __restrict__ bhh,
    const int*   __restrict__ seqp,
    float*       __restrict__ out)
{
    extern __shared__ char sm[];
    __half* sW  = (__half*)sm;                  // [4][64][32][8]
    float*  red = (float*)(sm + SMEM_W);        // [8 warps][16 rows][64 cols]

    const int tid  = threadIdx.x;
    const int cta  = blockIdx.x;
    const int w    = tid >> 5;
    const int lane = tid & 31;

    // load resident W fragments (131072 B = 8192 uint4)
    {
        const uint4* src = (const uint4*)&g_WP[(size_t)cta * 65536];
        uint4* dst = (uint4*)sW;
#pragma unroll 4
        for (int i = tid; i < 8192; i += NTHR) dst[i] = src[i];
    }

    // epilogue mapping: thread -> (unit j, batch c)
    const int j = tid >> 6;
    const int c = tid & 63;
    const int u = cta * 4 + j;
    const int xo = xoff(u, c);   // publish offset in packed planes

    float cst[NL];
#pragma unroll
    for (int l = 0; l < NL; l++)
        cst[l] = c0[(size_t)l * Bz * Hd + c * Hd + u];

    float bias[NL][4];
#pragma unroll
    for (int l = 0; l < NL; l++)
#pragma unroll
        for (int g = 0; g < 4; g++)
            bias[l][g] = bih[l * 4 * Hd + g * Hd + u] + bhh[l * 4 * Hd + g * Hd + u];

    int T = Tmax;
    if (seqp) { int tv = *seqp; if (tv > 0 && tv <= Tmax) T = tv; }
    const int R = NL * T;

    __syncthreads();

    const int kt0 = w * 4;                       // plane-local first ktile for this warp
    const uint4* sA0 = (const uint4*)sW;

    float acc[8][4];
#pragma unroll
    for (int nt = 0; nt < 8; nt++)
#pragma unroll
        for (int q = 0; q < 4; q++) acc[nt][q] = 0.f;

    // Hrec half for round 0 (t=0, l=0, p=0): reads prologue-packed data
    half_mma(acc, sA0 + (0 * 64 + 32 + kt0) * 32 + lane,
             (const uint2*)&g_Hrec[0][0][0], kt0, lane);

    for (int r = 0; r < R; r++) {
        const int t = r >> 2, l = r & 3, p = t & 1;

        // wait(r-1): all CTAs finished round r-1 -> Xin plane for round r is ready
        if (r > 0) {
            if (tid == 0) {
                const unsigned target = (unsigned)r * NCTA;
                volatile unsigned* vb = &g_bar;
                while (*vb < target) { }
            }
            __syncthreads();
        }

        // Xin half of round r (critical path)
        half_mma(acc, sA0 + (l * 64 + kt0) * 32 + lane,
                 (const uint2*)&g_Xin[p][l][0], kt0, lane);

        // cross-warp K reduction via smem
        {
            int gid = lane >> 2, tig = lane & 3;
#pragma unroll
            for (int nt = 0; nt < 8; nt++) {
                *(float2*)&red[(w * 16 + gid)     * 64 + nt * 8 + tig * 2] =
                    make_float2(acc[nt][0], acc[nt][1]);
                *(float2*)&red[(w * 16 + gid + 8) * 64 + nt * 8 + tig * 2] =
                    make_float2(acc[nt][2], acc[nt][3]);
            }
        }
        __syncthreads();

        float s0 = 0.f, s1 = 0.f, s2 = 0.f, s3 = 0.f;
#pragma unroll
        for (int ww = 0; ww < 8; ww++) {
            const float* rw = &red[(ww * 16 + j * 4) * 64 + c];
            s0 += rw[0]; s1 += rw[64]; s2 += rw[128]; s3 += rw[192];
        }

        float iG = sigm(s0 + bias[l][0]);
        float fG = sigm(s1 + bias[l][1]);
        float gG = tanhf(s2 + bias[l][2]);
        float oG = sigm(s3 + bias[l][3]);
        float cn = fG * cst[l] + iG * gG;
        cst[l] = cn;
        float hn = oG * tanhf(cn);

        // publish h (single fp16): next-layer input slot + own recurrent slot
        {
            unsigned short hb = __half_as_ushort(__float2half_rn(hn));
            __half* xdst = (l < NL - 1) ? &g_Xin[p][l + 1][0] : &g_Xin[p ^ 1][0][0];
            __stcg((unsigned short*)&xdst[xo], hb);
            __stcg((unsigned short*)&g_Hrec[p ^ 1][l][xo], hb);
        }
        if (l == NL - 1)
            out[((size_t)c * T + t) * Hd + u] = hn;   // out[b][t][u]

        __threadfence();
        __syncthreads();           // all publishes done; also guards red reuse
        if (tid == 0) atomicAdd(&g_bar, 1u);   // arrive(r)

        // Hrec half of round r+1 — runs in the shadow of other CTAs' skew.
        // Its source was written at round r-3, already ordered by wait(r-1).
        if (r + 1 < R) {
#pragma unroll
            for (int nt = 0; nt < 8; nt++)
#pragma unroll
                for (int q = 0; q < 4; q++) acc[nt][q] = 0.f;
            const int r2 = r + 1, l2 = r2 & 3, p2 = (r2 >> 2) & 1;
            half_mma(acc, sA0 + (l2 * 64 + 32 + kt0) * 32 + lane,
                     (const uint2*)&g_Hrec[p2][l2][0], kt0, lane);
        }
    }
}

extern "C" void kernel_launch(void* const* d_in, const int* in_sizes, int n_in,
                              void* d_out, int out_size) {
    const float* y   = (const float*)d_in[0];
    const float* h0  = (const float*)d_in[1];
    const float* c0  = (const float*)d_in[2];
    const float* Wih = (const float*)d_in[3];
    const float* Whh = (const float*)d_in[4];
    const float* bih = (const float*)d_in[5];
    const float* bhh = (const float*)d_in[6];
    const int*   sl  = (n_in >= 8) ? (const int*)d_in[7] : nullptr;
    float* out = (float*)d_out;
    (void)in_sizes; (void)out_size;

    cudaFuncSetAttribute(lstm_mma, cudaFuncAttributeMaxDynamicSharedMemorySize, SMEM_TOT);

    pack_weights<<<32768, 256>>>(Wih, Whh);
    pack_state<<<640, 256>>>(y, h0);
    lstm_mma<<<NCTA, NTHR, SMEM_TOT>>>(c0, bih, bhh, sl, out);
}

// round 10
// speedup vs baseline: 5.5086x; 1.0908x over previous
#include <cuda_runtime.h>
#include <cuda_fp16.h>
#include <stdint.h>

// Problem constants (fixed by dataset)
#define NL    4
#define Bz    64
#define Hd    512
#define Tmax  256
#define NCTA  128
#define NTHR  256

#define RSTRIDE 66                       // padded row stride for reduction buf
#define SMEM_W   (4*64*32*16)            // 131072 B: A-fragments, 4 layers x 64 ktiles
#define SMEM_RED (4*16*RSTRIDE*4)        // 16896 B
#define SMEM_TOT (SMEM_W + SMEM_RED)

// ---------------- persistent device state (no allocation allowed) ----------------
// Activations packed in B-fragment order, single fp16, 8B/lane = {b0,b1}
// plane = [32 ktiles][8 ntiles][32 lanes][4 halves] = 32768 halves
__device__ __align__(16) __half g_Xin [2][NL][32768];  // input to layer l, parity p
__device__ __align__(16) __half g_Hrec[2][NL][32768];  // recurrent h of layer l, parity p
__device__ unsigned g_bar;                             // monotonic; self-reset at end

// fast-math activations (MUFU-based, ~1e-6 rel err)
__device__ __forceinline__ float sigm(float x) {
    return __fdividef(1.0f, 1.0f + __expf(-x));
}
__device__ __forceinline__ float tanhfast(float x) {
    return __fdividef(2.0f, 1.0f + __expf(-2.0f * x)) - 1.0f;
}

// offset of X element (k,n) inside a packed plane (single fp16)
__device__ __forceinline__ int xoff(int k, int n) {
    int kt = k >> 4, kr = k & 15, nt = n >> 3, nc = n & 7;
    int lane = nc * 4 + ((kr >> 1) & 3);
    return ((kt * 8 + nt) * 32 + lane) * 4 + ((kr >> 3) * 2 + (kr & 1));
}

__device__ __forceinline__ void mma16816(float* c,
                                         unsigned a0, unsigned a1, unsigned a2, unsigned a3,
                                         unsigned b0, unsigned b1) {
    asm volatile(
        "mma.sync.aligned.m16n8k16.row.col.f32.f16.f16.f32 "
        "{%0,%1,%2,%3}, {%4,%5,%6,%7}, {%8,%9}, {%0,%1,%2,%3};\n"
        : "+f"(c[0]), "+f"(c[1]), "+f"(c[2]), "+f"(c[3])
        : "r"(a0), "r"(a1), "r"(a2), "r"(a3), "r"(b0), "r"(b1));
}

// ---- half-GEMM: 8 ktiles x 4 ntiles, full B preload (max MLP), acc carried ----
__device__ __forceinline__ void half_mma(
    float acc[4][4], const uint4* __restrict__ sA,
    const uint2* __restrict__ Bp, int kt0, int nt0, int lane)
{
    uint2 bb[8][4];
#pragma unroll
    for (int q = 0; q < 8; q++)
#pragma unroll
        for (int n = 0; n < 4; n++)
            bb[q][n] = __ldcg(Bp + (((kt0 + q) * 8 + nt0 + n) * 32 + lane));
#pragma unroll
    for (int q = 0; q < 8; q++) {
        uint4 a = sA[q * 32];
#pragma unroll
        for (int n = 0; n < 4; n++)
            mma16816(acc[n], a.x, a.y, a.z, a.w, bb[q][n].x, bb[q][n].y);
    }
}

// ---------------- single persistent kernel (prologue folded in) ----------------
// CTA owns 16 gate rows (4 units x 4 gates). Warp w: kquad = w&3 (8 ktiles per
// half), nhalf = w>>2 (4 ntiles). Hrec half of round r+1 runs after arrive(r).
__global__ void __launch_bounds__(NTHR, 1) lstm_all(
    const float* __restrict__ y,
    const float* __restrict__ h0,
    const float* __restrict__ c0,
    const float* __restrict__ Wih,
    const float* __restrict__ Whh,
    const float* __restrict__ bih,
    const float* __restrict__ bhh,
    const int*   __restrict__ seqp,
    float*       __restrict__ out)
{
    extern __shared__ char sm[];
    __half* sW  = (__half*)sm;            // [4][64][32] uint4 A-fragments
    float*  red = (float*)(sm + SMEM_W);  // [4 kquads][16 rows][RSTRIDE]

    const int tid  = threadIdx.x;
    const int cta  = blockIdx.x;
    const int w    = tid >> 5;
    const int lane = tid & 31;
    const int u0   = cta * 4;

    // ---- prologue A: pack this CTA's weights straight into smem (fp16 frags) ----
#pragma unroll 4
    for (int i = 0; i < 32; i++) {
        int idx = i * NTHR + tid;                 // 0..8191 = ((l*64+kt)*32+ln)
        int ln = idx & 31, kt = (idx >> 5) & 63, l = idx >> 11;
        const float* W = ((kt < 32) ? Wih : Whh) + (size_t)l * 4 * Hd * Hd;
        int kb = (kt & 31) * 16 + (ln & 3) * 2;
        __half h8[8];
#pragma unroll
        for (int areg = 0; areg < 4; areg++) {
            int r = (ln >> 2) + (areg & 1) * 8;   // A row 0..15
            int grow = (r & 3) * Hd + u0 + (r >> 2);
            float2 v = *(const float2*)&W[(size_t)grow * Hd + kb + (areg >> 1) * 8];
            h8[areg * 2 + 0] = __float2half_rn(v.x);
            h8[areg * 2 + 1] = __float2half_rn(v.y);
        }
        *(uint4*)&sW[(size_t)idx * 8] = *(uint4*)h8;
    }

    // ---- prologue B: pack initial state (grid-strided) ----
    for (int i = cta * NTHR + tid; i < (NL + 1) * Hd * Bz; i += NCTA * NTHR) {
        int u = (i & 32767) >> 6, b = i & 63;
        if (i < Hd * Bz)
            g_Xin[0][0][xoff(u, b)] = __float2half_rn(y[b * Hd + u]);
        else {
            int l = (i >> 15) - 1;
            g_Hrec[0][l][xoff(u, b)] =
                __float2half_rn(h0[(size_t)l * Bz * Hd + b * Hd + u]);
        }
    }

    // epilogue mapping: thread -> (unit j, batch c)
    const int j = tid >> 6;
    const int c = tid & 63;
    const int u = u0 + j;
    const int xo = xoff(u, c);

    float cst[NL];
#pragma unroll
    for (int l = 0; l < NL; l++)
        cst[l] = c0[(size_t)l * Bz * Hd + c * Hd + u];

    float bias[NL][4];
#pragma unroll
    for (int l = 0; l < NL; l++)
#pragma unroll
        for (int g = 0; g < 4; g++)
            bias[l][g] = bih[l * 4 * Hd + g * Hd + u] + bhh[l * 4 * Hd + g * Hd + u];

    int T = Tmax;
    if (seqp) { int tv = *seqp; if (tv > 0 && tv <= Tmax) T = tv; }
    const int R = NL * T;

    // ---- prologue grid barrier (also orders smem W pack within CTA) ----
    __syncthreads();
    __threadfence();
    if (tid == 0) {
        atomicAdd(&g_bar, 1u);
        volatile unsigned* vb = &g_bar;
        while (*vb < NCTA) { }
    }
    __syncthreads();

    // warp roles
    const int kq  = w & 3;          // K quadrant (8 ktiles per half)
    const int nt0 = (w >> 2) * 4;   // first ntile of this warp's N half
    const int kt0 = kq * 8;         // plane-local first ktile
    const uint4* sA0 = (const uint4*)sW;

    float acc[4][4];
#pragma unroll
    for (int n = 0; n < 4; n++)
#pragma unroll
        for (int q = 0; q < 4; q++) acc[n][q] = 0.f;

    // Hrec half for round 0 (t=0, l=0, p=0)
    half_mma(acc, sA0 + (0 * 64 + 32 + kt0) * 32 + lane,
             (const uint2*)&g_Hrec[0][0][0], kt0, nt0, lane);

    for (int r = 0; r < R; r++) {
        const int t = r >> 2, l = r & 3, p = t & 1;

        // wait(r-1): Xin plane for round r ready (prologue barrier covers r=0)
        if (r > 0) {
            if (tid == 0) {
                const unsigned target = (unsigned)(r + 1) * NCTA;
                volatile unsigned* vb = &g_bar;
                while (*vb < target) { }
            }
            __syncthreads();
        }

        // Xin half of round r (critical path)
        half_mma(acc, sA0 + (l * 64 + kt0) * 32 + lane,
                 (const uint2*)&g_Xin[p][l][0], kt0, nt0, lane);

        // cross-warp K reduction (4-way) via smem
        {
            int gid = lane >> 2, tig = lane & 3;
#pragma unroll
            for (int n = 0; n < 4; n++) {
                int col = (nt0 + n) * 8 + tig * 2;
                *(float2*)&red[(kq * 16 + gid)     * RSTRIDE + col] =
                    make_float2(acc[n][0], acc[n][1]);
                *(float2*)&red[(kq * 16 + gid + 8) * RSTRIDE + col] =
                    make_float2(acc[n][2], acc[n][3]);
            }
        }
        __syncthreads();

        float s0 = 0.f, s1 = 0.f, s2 = 0.f, s3 = 0.f;
#pragma unroll
        for (int kk = 0; kk < 4; kk++) {
            const float* rw = &red[(kk * 16 + j * 4) * RSTRIDE + c];
            s0 += rw[0];
            s1 += rw[RSTRIDE];
            s2 += rw[2 * RSTRIDE];
            s3 += rw[3 * RSTRIDE];
        }

        float iG = sigm(s0 + bias[l][0]);
        float fG = sigm(s1 + bias[l][1]);
        float gG = tanhfast(s2 + bias[l][2]);
        float oG = sigm(s3 + bias[l][3]);
        float cn = fG * cst[l] + iG * gG;
        cst[l] = cn;
        float hn = oG * tanhfast(cn);

        // publish h (single fp16): next-layer input slot + own recurrent slot
        {
            unsigned short hb = __half_as_ushort(__float2half_rn(hn));
            __half* xdst = (l < NL - 1) ? &g_Xin[p][l + 1][0] : &g_Xin[p ^ 1][0][0];
            __stcg((unsigned short*)&xdst[xo], hb);
            __stcg((unsigned short*)&g_Hrec[p ^ 1][l][xo], hb);
        }
        if (l == NL - 1)
            out[((size_t)c * T + t) * Hd + u] = hn;   // out[b][t][u]

        __threadfence();
        __syncthreads();           // publishes done; also guards red reuse
        if (tid == 0) atomicAdd(&g_bar, 1u);   // arrive(r)

        // Hrec half of round r+1 (source written at round r-3, already ordered)
        if (r + 1 < R) {
#pragma unroll
            for (int n = 0; n < 4; n++)
#pragma unroll
                for (int q = 0; q < 4; q++) acc[n][q] = 0.f;
            const int r2 = r + 1, l2 = r2 & 3, p2 = (r2 >> 2) & 1;
            half_mma(acc, sA0 + (l2 * 64 + 32 + kt0) * 32 + lane,
                     (const uint2*)&g_Hrec[p2][l2][0], kt0, nt0, lane);
        }
    }

    // self-reset barrier for next graph replay (deterministic state)
    if (cta == 0 && tid == 0) {
        volatile unsigned* vb = &g_bar;
        while (*vb < (unsigned)(R + 1) * NCTA) { }
        *vb = 0u;
    }
}

extern "C" void kernel_launch(void* const* d_in, const int* in_sizes, int n_in,
                              void* d_out, int out_size) {
    const float* y   = (const float*)d_in[0];
    const float* h0  = (const float*)d_in[1];
    const float* c0  = (const float*)d_in[2];
    const float* Wih = (const float*)d_in[3];
    const float* Whh = (const float*)d_in[4];
    const float* bih = (const float*)d_in[5];
    const float* bhh = (const float*)d_in[6];
    const int*   sl  = (n_in >= 8) ? (const int*)d_in[7] : nullptr;
    float* out = (float*)d_out;
    (void)in_sizes; (void)out_size;

    cudaFuncSetAttribute(lstm_all, cudaFuncAttributeMaxDynamicSharedMemorySize, SMEM_TOT);
    lstm_all<<<NCTA, NTHR, SMEM_TOT>>>(y, h0, c0, Wih, Whh, bih, bhh, sl, out);
}